// round 2
// baseline (speedup 1.0000x reference)
#include <cuda_runtime.h>

// Problem constants
#define NN 50000
#define EE 800000
// H = 64 feature dim throughout hidden layers

// ---------------- device scratch (no allocations allowed) ----------------
__device__ float g_y[NN * 64];     // pre-aggregation GEMM output (gather source)
__device__ float g_agg[NN * 64];   // aggregation accumulator
__device__ float g_h[NN * 64];     // post-MLP (pre-BN) features
__device__ float g_stats[128];     // [0:64) sum, [64:128) sumsq
__device__ float g_scale[64];
__device__ float g_shift[64];

// ---------------------------------------------------------------------------
// Kernel A: y = act(src) @ W  (N x K @ K x 64), where act = identity (layer 1)
// or BN(scale,shift)+ReLU (layers 2,3, reading g_h). Writes g_y and
// g_agg = (1+eps)*y. Block computes a 64x64 tile with 4x4 register tiles.
// Block 0 also zeroes g_stats for the upcoming mlpB.
// ---------------------------------------------------------------------------
template <int K, bool BN>
__global__ void __launch_bounds__(256) gemmA(const float* __restrict__ A,
                                             const float* __restrict__ W,
                                             const float* __restrict__ epsp) {
    __shared__ float As[64][64];
    __shared__ float4 Ws[64][16];

    const int tid = threadIdx.x;
    const int row0 = blockIdx.x * 64;
    const int tr = tid >> 4;    // 0..15
    const int tc = tid & 15;    // 0..15

    const float* __restrict__ src = BN ? (const float*)g_h : A;

    float acc[4][4] = {};

    for (int kc = 0; kc < K; kc += 64) {
        // load A tile (64 rows x 64 k), applying BN+ReLU if requested
#pragma unroll
        for (int l = 0; l < 4; l++) {
            int idx = tid + l * 256;
            int r = idx >> 4;
            int k4 = (idx & 15) << 2;
            int gr = row0 + r;
            float4 v = make_float4(0.f, 0.f, 0.f, 0.f);
            if (gr < NN)
                v = *reinterpret_cast<const float4*>(&src[gr * K + kc + k4]);
            if (BN) {
                int kk = kc + k4;
                v.x = fmaxf(fmaf(v.x, g_scale[kk + 0], g_shift[kk + 0]), 0.f);
                v.y = fmaxf(fmaf(v.y, g_scale[kk + 1], g_shift[kk + 1]), 0.f);
                v.z = fmaxf(fmaf(v.z, g_scale[kk + 2], g_shift[kk + 2]), 0.f);
                v.w = fmaxf(fmaf(v.w, g_scale[kk + 3], g_shift[kk + 3]), 0.f);
            }
            *reinterpret_cast<float4*>(&As[r][k4]) = v;
        }
        // load W tile (64 k x 64 cols)
#pragma unroll
        for (int l = 0; l < 4; l++) {
            int idx = tid + l * 256;  // 0..1023
            int k = idx >> 4;
            int c4 = idx & 15;
            Ws[k][c4] = *reinterpret_cast<const float4*>(&W[(kc + k) * 64 + c4 * 4]);
        }
        __syncthreads();

#pragma unroll
        for (int k4 = 0; k4 < 16; k4++) {
            float4 a[4], w[4];
#pragma unroll
            for (int i = 0; i < 4; i++)
                a[i] = *reinterpret_cast<const float4*>(&As[tr * 4 + i][k4 * 4]);
#pragma unroll
            for (int j = 0; j < 4; j++) w[j] = Ws[k4 * 4 + j][tc];
#pragma unroll
            for (int i = 0; i < 4; i++) {
                const float* ap = &a[i].x;
#pragma unroll
                for (int j = 0; j < 4; j++) {
                    const float* wp = &w[j].x;
                    float av = ap[j];
#pragma unroll
                    for (int c = 0; c < 4; c++) acc[i][c] = fmaf(av, wp[c], acc[i][c]);
                }
            }
        }
        __syncthreads();
    }

    const float ep = 1.f + *epsp;
#pragma unroll
    for (int i = 0; i < 4; i++) {
        int gr = row0 + tr * 4 + i;
        if (gr < NN) {
            float4 v = make_float4(acc[i][0], acc[i][1], acc[i][2], acc[i][3]);
            reinterpret_cast<float4*>(g_y)[gr * 16 + tc] = v;
            float4 va = make_float4(ep * acc[i][0], ep * acc[i][1],
                                    ep * acc[i][2], ep * acc[i][3]);
            reinterpret_cast<float4*>(g_agg)[gr * 16 + tc] = va;
        }
    }
    if (blockIdx.x == 0 && tid < 128) g_stats[tid] = 0.f;
}

// ---------------------------------------------------------------------------
// Scatter: g_agg[dst] += g_y[src], 64 floats per edge, one float4 per thread.
// grid*block == EE*16 exactly. edge_index arrives as int32 (harness converts
// int64 inputs to int32).
// ---------------------------------------------------------------------------
__global__ void __launch_bounds__(256) scatterK(const int* __restrict__ ei) {
    int idx = blockIdx.x * 256 + threadIdx.x;
    int e = idx >> 4;
    int q = idx & 15;
    int s = ei[e];
    int d = ei[EE + e];
    float4 v = reinterpret_cast<const float4*>(g_y)[s * 16 + q];
    float* dst = &g_agg[d * 64 + (q << 2)];
    atomicAdd(dst + 0, v.x);
    atomicAdd(dst + 1, v.y);
    atomicAdd(dst + 2, v.z);
    atomicAdd(dst + 3, v.w);
}

// ---------------------------------------------------------------------------
// Kernel B: h1 = relu(agg + ba); h2 = relu(h1 @ Wb + bb); write g_h and
// accumulate column sum / sumsq into g_stats (block partials -> atomics).
// ---------------------------------------------------------------------------
__global__ void __launch_bounds__(256) mlpB(const float* __restrict__ W,
                                            const float* __restrict__ ba,
                                            const float* __restrict__ bb) {
    __shared__ float As[64][64];
    __shared__ float4 Ws[64][16];
    __shared__ float ssum[64];
    __shared__ float ssq[64];

    const int tid = threadIdx.x;
    const int row0 = blockIdx.x * 64;
    const int tr = tid >> 4;
    const int tc = tid & 15;

    if (tid < 64) { ssum[tid] = 0.f; ssq[tid] = 0.f; }

#pragma unroll
    for (int l = 0; l < 4; l++) {
        int idx = tid + l * 256;
        {
            int r = idx >> 4;
            int k4 = (idx & 15) << 2;
            int gr = row0 + r;
            float4 v = make_float4(0.f, 0.f, 0.f, 0.f);
            if (gr < NN) {
                v = *reinterpret_cast<const float4*>(&g_agg[gr * 64 + k4]);
                float4 b = *reinterpret_cast<const float4*>(&ba[k4]);
                v.x = fmaxf(v.x + b.x, 0.f);
                v.y = fmaxf(v.y + b.y, 0.f);
                v.z = fmaxf(v.z + b.z, 0.f);
                v.w = fmaxf(v.w + b.w, 0.f);
            }
            *reinterpret_cast<float4*>(&As[r][k4]) = v;
        }
        {
            int k = idx >> 4;
            int c4 = idx & 15;
            Ws[k][c4] = *reinterpret_cast<const float4*>(&W[k * 64 + c4 * 4]);
        }
    }
    __syncthreads();

    float acc[4][4] = {};
#pragma unroll
    for (int k4 = 0; k4 < 16; k4++) {
        float4 a[4], w[4];
#pragma unroll
        for (int i = 0; i < 4; i++)
            a[i] = *reinterpret_cast<const float4*>(&As[tr * 4 + i][k4 * 4]);
#pragma unroll
        for (int j = 0; j < 4; j++) w[j] = Ws[k4 * 4 + j][tc];
#pragma unroll
        for (int i = 0; i < 4; i++) {
            const float* ap = &a[i].x;
#pragma unroll
            for (int j = 0; j < 4; j++) {
                const float* wp = &w[j].x;
                float av = ap[j];
#pragma unroll
                for (int c = 0; c < 4; c++) acc[i][c] = fmaf(av, wp[c], acc[i][c]);
            }
        }
    }

    float4 bbv = *reinterpret_cast<const float4*>(&bb[tc * 4]);
    const float bbl[4] = {bbv.x, bbv.y, bbv.z, bbv.w};
    float csum[4] = {}, csq[4] = {};
#pragma unroll
    for (int i = 0; i < 4; i++) {
        int gr = row0 + tr * 4 + i;
        float h0 = fmaxf(acc[i][0] + bbl[0], 0.f);
        float h1 = fmaxf(acc[i][1] + bbl[1], 0.f);
        float h2 = fmaxf(acc[i][2] + bbl[2], 0.f);
        float h3 = fmaxf(acc[i][3] + bbl[3], 0.f);
        if (gr < NN) {
            reinterpret_cast<float4*>(g_h)[gr * 16 + tc] = make_float4(h0, h1, h2, h3);
            csum[0] += h0; csum[1] += h1; csum[2] += h2; csum[3] += h3;
            csq[0] += h0 * h0; csq[1] += h1 * h1; csq[2] += h2 * h2; csq[3] += h3 * h3;
        }
    }
#pragma unroll
    for (int c = 0; c < 4; c++) {
        atomicAdd(&ssum[tc * 4 + c], csum[c]);
        atomicAdd(&ssq[tc * 4 + c], csq[c]);
    }
    __syncthreads();
    if (tid < 64) {
        atomicAdd(&g_stats[tid], ssum[tid]);
        atomicAdd(&g_stats[64 + tid], ssq[tid]);
    }
}

// ---------------------------------------------------------------------------
// BN prep: fold mean/var/gamma/beta into per-feature scale/shift.
// ---------------------------------------------------------------------------
__global__ void bnprep(const float* __restrict__ g, const float* __restrict__ be) {
    int c = threadIdx.x;
    const float inv = 1.f / (float)NN;
    float mean = g_stats[c] * inv;
    float var = g_stats[64 + c] * inv - mean * mean;
    float sc = g[c] * rsqrtf(var + 1e-5f);
    g_scale[c] = sc;
    g_shift[c] = be[c] - mean * sc;
}

// ---------------------------------------------------------------------------
// Final head: out = relu(BN(g_h)) @ lin_w + lin_b  (64 -> 10)
// ---------------------------------------------------------------------------
__global__ void __launch_bounds__(256) finalLin(const float* __restrict__ lw,
                                                const float* __restrict__ lb,
                                                float* __restrict__ out) {
    __shared__ float ws[64][10];
    __shared__ float sc[64], sh[64];
    __shared__ float lbs[10];
    int tid = threadIdx.x;
    for (int i = tid; i < 640; i += 256) ws[i / 10][i % 10] = lw[i];
    if (tid < 64) { sc[tid] = g_scale[tid]; sh[tid] = g_shift[tid]; }
    if (tid < 10) lbs[tid] = lb[tid];
    __syncthreads();

    int r = blockIdx.x * 256 + tid;
    if (r >= NN) return;
    float acc[10];
#pragma unroll
    for (int c = 0; c < 10; c++) acc[c] = lbs[c];
#pragma unroll 16
    for (int k = 0; k < 64; k++) {
        float hv = fmaxf(fmaf(g_h[r * 64 + k], sc[k], sh[k]), 0.f);
#pragma unroll
        for (int c = 0; c < 10; c++) acc[c] = fmaf(hv, ws[k][c], acc[c]);
    }
#pragma unroll
    for (int c = 0; c < 10; c++) out[r * 10 + c] = acc[c];
}

// ---------------------------------------------------------------------------
extern "C" void kernel_launch(void* const* d_in, const int* in_sizes, int n_in,
                              void* d_out, int out_size) {
    const float* x    = (const float*)d_in[0];
    const int* ei     = (const int*)d_in[1];   // int64 inputs delivered as int32
    const float* eps1 = (const float*)d_in[2];
    const float* w1a  = (const float*)d_in[3];
    const float* b1a  = (const float*)d_in[4];
    const float* w1b  = (const float*)d_in[5];
    const float* b1b  = (const float*)d_in[6];
    const float* g1   = (const float*)d_in[7];
    const float* be1  = (const float*)d_in[8];
    const float* eps2 = (const float*)d_in[9];
    const float* w2a  = (const float*)d_in[10];
    const float* b2a  = (const float*)d_in[11];
    const float* w2b  = (const float*)d_in[12];
    const float* b2b  = (const float*)d_in[13];
    const float* g2   = (const float*)d_in[14];
    const float* be2  = (const float*)d_in[15];
    const float* eps3 = (const float*)d_in[16];
    const float* w3a  = (const float*)d_in[17];
    const float* b3a  = (const float*)d_in[18];
    const float* w3b  = (const float*)d_in[19];
    const float* b3b  = (const float*)d_in[20];
    const float* g3   = (const float*)d_in[21];
    const float* be3  = (const float*)d_in[22];
    const float* lw   = (const float*)d_in[23];
    const float* lb   = (const float*)d_in[24];
    float* out = (float*)d_out;

    const int gb = (NN + 63) / 64;            // 782 row-tiles
    const int sg = (EE * 16) / 256;           // 50000 scatter blocks

    // Layer 1 (K = 128, input = x, no BN on input)
    gemmA<128, false><<<gb, 256>>>(x, w1a, eps1);
    scatterK<<<sg, 256>>>(ei);
    mlpB<<<gb, 256>>>(w1b, b1a, b1b);
    bnprep<<<1, 64>>>(g1, be1);

    // Layer 2 (input = relu(BN(g_h)) applied on the fly)
    gemmA<64, true><<<gb, 256>>>(nullptr, w2a, eps2);
    scatterK<<<sg, 256>>>(ei);
    mlpB<<<gb, 256>>>(w2b, b2a, b2b);
    bnprep<<<1, 64>>>(g2, be2);

    // Layer 3
    gemmA<64, true><<<gb, 256>>>(nullptr, w3a, eps3);
    scatterK<<<sg, 256>>>(ei);
    mlpB<<<gb, 256>>>(w3b, b3a, b3b);
    bnprep<<<1, 64>>>(g3, be3);

    // Head
    finalLin<<<(NN + 255) / 256, 256>>>(lw, lb, out);
}

// round 4
// speedup vs baseline: 1.8327x; 1.8327x over previous
#include <cuda_runtime.h>

// Problem constants
#define NN 50000
#define EE 800000
// H = 64 feature dim throughout hidden layers

// ---------------- device scratch (no allocations allowed) ----------------
__device__ __align__(16) float g_y[NN * 64];     // pre-aggregation GEMM output
__device__ __align__(16) float g_agg[NN * 64];   // aggregation accumulator
__device__ __align__(16) float g_h[NN * 64];     // post-MLP (pre-BN) features
__device__ float g_stats[128];                   // [0:64) sum, [64:128) sumsq

// ---------------------------------------------------------------------------
// Kernel A: y = act(src) @ W  (N x K @ K x 64), act = identity (layer 1) or
// BN+ReLU (layers 2,3; scale/shift computed in-block from g_stats + gamma,
// beta). Writes g_y and g_agg = (1+eps)*y. 64x64 block tile, 4x4 reg tiles.
// ---------------------------------------------------------------------------
template <int K, bool BN>
__global__ void __launch_bounds__(256) gemmA(const float* __restrict__ A,
                                             const float* __restrict__ W,
                                             const float* __restrict__ epsp,
                                             const float* __restrict__ gamma,
                                             const float* __restrict__ beta) {
    __shared__ float As[64][64];
    __shared__ float4 Ws[64][16];
    __shared__ float sc[64], sh[64];

    const int tid = threadIdx.x;
    const int row0 = blockIdx.x * 64;
    const int tr = tid >> 4;    // 0..15
    const int tc = tid & 15;    // 0..15

    const float* __restrict__ src = BN ? (const float*)g_h : A;

    if (BN) {
        if (tid < 64) {
            const float inv = 1.f / (float)NN;
            float mean = g_stats[tid] * inv;
            float var = g_stats[64 + tid] * inv - mean * mean;
            float s = gamma[tid] * rsqrtf(var + 1e-5f);
            sc[tid] = s;
            sh[tid] = beta[tid] - mean * s;
        }
        __syncthreads();
    }

    float acc[4][4] = {};

    for (int kc = 0; kc < K; kc += 64) {
        // load A tile (64 rows x 64 k), applying BN+ReLU if requested
#pragma unroll
        for (int l = 0; l < 4; l++) {
            int idx = tid + l * 256;
            int r = idx >> 4;
            int k4 = (idx & 15) << 2;
            int gr = row0 + r;
            float4 v = make_float4(0.f, 0.f, 0.f, 0.f);
            if (gr < NN)
                v = *reinterpret_cast<const float4*>(&src[gr * K + kc + k4]);
            if (BN) {
                v.x = fmaxf(fmaf(v.x, sc[k4 + 0], sh[k4 + 0]), 0.f);
                v.y = fmaxf(fmaf(v.y, sc[k4 + 1], sh[k4 + 1]), 0.f);
                v.z = fmaxf(fmaf(v.z, sc[k4 + 2], sh[k4 + 2]), 0.f);
                v.w = fmaxf(fmaf(v.w, sc[k4 + 3], sh[k4 + 3]), 0.f);
            }
            *reinterpret_cast<float4*>(&As[r][k4]) = v;
        }
        // load W tile (64 k x 64 cols)
#pragma unroll
        for (int l = 0; l < 4; l++) {
            int idx = tid + l * 256;  // 0..1023
            int k = idx >> 4;
            int c4 = idx & 15;
            Ws[k][c4] = *reinterpret_cast<const float4*>(&W[(kc + k) * 64 + c4 * 4]);
        }
        __syncthreads();

#pragma unroll
        for (int k4 = 0; k4 < 16; k4++) {
            float4 a[4], w[4];
#pragma unroll
            for (int i = 0; i < 4; i++)
                a[i] = *reinterpret_cast<const float4*>(&As[tr * 4 + i][k4 * 4]);
#pragma unroll
            for (int j = 0; j < 4; j++) w[j] = Ws[k4 * 4 + j][tc];
#pragma unroll
            for (int i = 0; i < 4; i++) {
                const float* ap = &a[i].x;
#pragma unroll
                for (int j = 0; j < 4; j++) {
                    const float* wp = &w[j].x;
                    float av = ap[j];
#pragma unroll
                    for (int c = 0; c < 4; c++) acc[i][c] = fmaf(av, wp[c], acc[i][c]);
                }
            }
        }
        __syncthreads();
    }

    const float ep = 1.f + *epsp;
#pragma unroll
    for (int i = 0; i < 4; i++) {
        int gr = row0 + tr * 4 + i;
        if (gr < NN) {
            float4 v = make_float4(acc[i][0], acc[i][1], acc[i][2], acc[i][3]);
            reinterpret_cast<float4*>(g_y)[gr * 16 + tc] = v;
            float4 va = make_float4(ep * acc[i][0], ep * acc[i][1],
                                    ep * acc[i][2], ep * acc[i][3]);
            reinterpret_cast<float4*>(g_agg)[gr * 16 + tc] = va;
        }
    }
}

// ---------------------------------------------------------------------------
// Scatter: g_agg[dst] += g_y[src], 64 floats per edge; one 16B vector RED per
// thread (16 threads per edge). Block 0 also zeroes g_stats for the upcoming
// mlpB (safe: runs between the stats reader gemmA and the stats writer mlpB).
// ---------------------------------------------------------------------------
__global__ void __launch_bounds__(256) scatterK(const int* __restrict__ ei) {
    int idx = blockIdx.x * 256 + threadIdx.x;
    int e = idx >> 4;
    int q = idx & 15;
    int s = __ldg(&ei[e]);
    int d = __ldg(&ei[EE + e]);
    float4 v = reinterpret_cast<const float4*>(g_y)[s * 16 + q];
    float* dst = &g_agg[d * 64 + (q << 2)];
    asm volatile("red.global.add.v4.f32 [%0], {%1, %2, %3, %4};"
                 :: "l"(dst), "f"(v.x), "f"(v.y), "f"(v.z), "f"(v.w)
                 : "memory");
    if (blockIdx.x == 0 && threadIdx.x < 128) g_stats[threadIdx.x] = 0.f;
}

// ---------------------------------------------------------------------------
// Kernel B: h1 = relu(agg + ba); h2 = relu(h1 @ Wb + bb); write g_h and
// accumulate column sum / sumsq into g_stats (block partials -> atomics).
// ---------------------------------------------------------------------------
__global__ void __launch_bounds__(256) mlpB(const float* __restrict__ W,
                                            const float* __restrict__ ba,
                                            const float* __restrict__ bb) {
    __shared__ float As[64][64];
    __shared__ float4 Ws[64][16];
    __shared__ float ssum[64];
    __shared__ float ssq[64];

    const int tid = threadIdx.x;
    const int row0 = blockIdx.x * 64;
    const int tr = tid >> 4;
    const int tc = tid & 15;

    if (tid < 64) { ssum[tid] = 0.f; ssq[tid] = 0.f; }

#pragma unroll
    for (int l = 0; l < 4; l++) {
        int idx = tid + l * 256;
        {
            int r = idx >> 4;
            int k4 = (idx & 15) << 2;
            int gr = row0 + r;
            float4 v = make_float4(0.f, 0.f, 0.f, 0.f);
            if (gr < NN) {
                v = *reinterpret_cast<const float4*>(&g_agg[gr * 64 + k4]);
                float4 b = *reinterpret_cast<const float4*>(&ba[k4]);
                v.x = fmaxf(v.x + b.x, 0.f);
                v.y = fmaxf(v.y + b.y, 0.f);
                v.z = fmaxf(v.z + b.z, 0.f);
                v.w = fmaxf(v.w + b.w, 0.f);
            }
            *reinterpret_cast<float4*>(&As[r][k4]) = v;
        }
        {
            int k = idx >> 4;
            int c4 = idx & 15;
            Ws[k][c4] = *reinterpret_cast<const float4*>(&W[k * 64 + c4 * 4]);
        }
    }
    __syncthreads();

    float acc[4][4] = {};
#pragma unroll
    for (int k4 = 0; k4 < 16; k4++) {
        float4 a[4], w[4];
#pragma unroll
        for (int i = 0; i < 4; i++)
            a[i] = *reinterpret_cast<const float4*>(&As[tr * 4 + i][k4 * 4]);
#pragma unroll
        for (int j = 0; j < 4; j++) w[j] = Ws[k4 * 4 + j][tc];
#pragma unroll
        for (int i = 0; i < 4; i++) {
            const float* ap = &a[i].x;
#pragma unroll
            for (int j = 0; j < 4; j++) {
                const float* wp = &w[j].x;
                float av = ap[j];
#pragma unroll
                for (int c = 0; c < 4; c++) acc[i][c] = fmaf(av, wp[c], acc[i][c]);
            }
        }
    }

    float4 bbv = *reinterpret_cast<const float4*>(&bb[tc * 4]);
    const float bbl[4] = {bbv.x, bbv.y, bbv.z, bbv.w};
    float csum[4] = {}, csq[4] = {};
#pragma unroll
    for (int i = 0; i < 4; i++) {
        int gr = row0 + tr * 4 + i;
        float h0 = fmaxf(acc[i][0] + bbl[0], 0.f);
        float h1 = fmaxf(acc[i][1] + bbl[1], 0.f);
        float h2 = fmaxf(acc[i][2] + bbl[2], 0.f);
        float h3 = fmaxf(acc[i][3] + bbl[3], 0.f);
        if (gr < NN) {
            reinterpret_cast<float4*>(g_h)[gr * 16 + tc] = make_float4(h0, h1, h2, h3);
            csum[0] += h0; csum[1] += h1; csum[2] += h2; csum[3] += h3;
            csq[0] += h0 * h0; csq[1] += h1 * h1; csq[2] += h2 * h2; csq[3] += h3 * h3;
        }
    }
#pragma unroll
    for (int c = 0; c < 4; c++) {
        atomicAdd(&ssum[tc * 4 + c], csum[c]);
        atomicAdd(&ssq[tc * 4 + c], csq[c]);
    }
    __syncthreads();
    if (tid < 64) {
        atomicAdd(&g_stats[tid], ssum[tid]);
        atomicAdd(&g_stats[64 + tid], ssq[tid]);
    }
}

// ---------------------------------------------------------------------------
// Final head: out = relu(BN(g_h)) @ lin_w + lin_b  (64 -> 10). BN scale/shift
// computed in-block from g_stats + gamma/beta.
// ---------------------------------------------------------------------------
__global__ void __launch_bounds__(256) finalLin(const float* __restrict__ lw,
                                                const float* __restrict__ lb,
                                                const float* __restrict__ gamma,
                                                const float* __restrict__ beta,
                                                float* __restrict__ out) {
    __shared__ float ws[64][10];
    __shared__ float sc[64], sh[64];
    __shared__ float lbs[10];
    int tid = threadIdx.x;
    for (int i = tid; i < 640; i += 256) ws[i / 10][i % 10] = lw[i];
    if (tid < 64) {
        const float inv = 1.f / (float)NN;
        float mean = g_stats[tid] * inv;
        float var = g_stats[64 + tid] * inv - mean * mean;
        float s = gamma[tid] * rsqrtf(var + 1e-5f);
        sc[tid] = s;
        sh[tid] = beta[tid] - mean * s;
    }
    if (tid < 10) lbs[tid] = lb[tid];
    __syncthreads();

    int r = blockIdx.x * 256 + tid;
    if (r >= NN) return;
    float acc[10];
#pragma unroll
    for (int c = 0; c < 10; c++) acc[c] = lbs[c];
#pragma unroll 16
    for (int k = 0; k < 64; k++) {
        float hv = fmaxf(fmaf(g_h[r * 64 + k], sc[k], sh[k]), 0.f);
#pragma unroll
        for (int c = 0; c < 10; c++) acc[c] = fmaf(hv, ws[k][c], acc[c]);
    }
#pragma unroll
    for (int c = 0; c < 10; c++) out[r * 10 + c] = acc[c];
}

// ---------------------------------------------------------------------------
extern "C" void kernel_launch(void* const* d_in, const int* in_sizes, int n_in,
                              void* d_out, int out_size) {
    const float* x    = (const float*)d_in[0];
    const int* ei     = (const int*)d_in[1];   // int64 inputs delivered as int32
    const float* eps1 = (const float*)d_in[2];
    const float* w1a  = (const float*)d_in[3];
    const float* b1a  = (const float*)d_in[4];
    const float* w1b  = (const float*)d_in[5];
    const float* b1b  = (const float*)d_in[6];
    const float* g1   = (const float*)d_in[7];
    const float* be1  = (const float*)d_in[8];
    const float* eps2 = (const float*)d_in[9];
    const float* w2a  = (const float*)d_in[10];
    const float* b2a  = (const float*)d_in[11];
    const float* w2b  = (const float*)d_in[12];
    const float* b2b  = (const float*)d_in[13];
    const float* g2   = (const float*)d_in[14];
    const float* be2  = (const float*)d_in[15];
    const float* eps3 = (const float*)d_in[16];
    const float* w3a  = (const float*)d_in[17];
    const float* b3a  = (const float*)d_in[18];
    const float* w3b  = (const float*)d_in[19];
    const float* b3b  = (const float*)d_in[20];
    const float* g3   = (const float*)d_in[21];
    const float* be3  = (const float*)d_in[22];
    const float* lw   = (const float*)d_in[23];
    const float* lb   = (const float*)d_in[24];
    float* out = (float*)d_out;

    const int gb = (NN + 63) / 64;            // 782 row-tiles
    const int sg = (EE * 16) / 256;           // 50000 scatter blocks

    // Layer 1 (K = 128, input = x, no BN on input)
    gemmA<128, false><<<gb, 256>>>(x, w1a, eps1, nullptr, nullptr);
    scatterK<<<sg, 256>>>(ei);
    mlpB<<<gb, 256>>>(w1b, b1a, b1b);

    // Layer 2 (input = relu(BN(g_h)) applied on the fly; stats from mlpB L1)
    gemmA<64, true><<<gb, 256>>>(nullptr, w2a, eps2, g1, be1);
    scatterK<<<sg, 256>>>(ei);
    mlpB<<<gb, 256>>>(w2b, b2a, b2b);

    // Layer 3
    gemmA<64, true><<<gb, 256>>>(nullptr, w3a, eps3, g2, be2);
    scatterK<<<sg, 256>>>(ei);
    mlpB<<<gb, 256>>>(w3b, b3a, b3b);

    // Head (BN of layer 3 applied on the fly)
    finalLin<<<(NN + 255) / 256, 256>>>(lw, lb, g3, be3, out);
}